// round 14
// baseline (speedup 1.0000x reference)
#include <cuda_runtime.h>
#include <math.h>

#define BS    8
#define NROT  60
#define NPTS  500
#define NBR   (BS * NROT)       // 480
#define HW    6400              // 80*80
#define NG    (NBR * NPTS)      // 240000 work items g = br*500 + n
#define NDU   (NG / 64)         // 3750 double-units of 64 consecutive g
#define GRID  148               // one block per SM
#define TPB   1024
#define CHUNK 5

// Scratch (allocation-free: __device__ globals)
__device__ float g_symA[NDU], g_symB[NDU];   // per-du segmented partials
__device__ float g_nsA[NDU],  g_nsB[NDU];
__device__ float g_scal[2];                  // [0]=loss_reg, [1]=loss_t
__device__ unsigned int g_cnt;               // completion counter

__device__ __forceinline__ void rot_point(
    const float* __restrict__ pred_r, const float* __restrict__ model_points,
    int br, int b, int n, float& px, float& py, float& pz, float& a2)
{
    const float* q = pred_r + (size_t)br * 4;
    float w = q[0], x = q[1], y = q[2], z = q[3];
    float r00 = 1.f - 2.f*(y*y + z*z);
    float r01 = 2.f*x*y - 2.f*w*z;
    float r02 = 2.f*w*y + 2.f*x*z;
    float r10 = 2.f*x*y + 2.f*z*w;
    float r11 = 1.f - 2.f*(x*x + z*z);
    float r12 = -2.f*w*x + 2.f*y*z;
    float r20 = -2.f*w*y + 2.f*x*z;
    float r21 = 2.f*w*x + 2.f*y*z;
    float r22 = 1.f - 2.f*(x*x + y*y);
    const float* mp = model_points + (size_t)b * NPTS * 3 + (size_t)n * 3;
    float mx = mp[0], my = mp[1], mz = mp[2];
    px = r00*mx + r01*my + r02*mz;
    py = r10*mx + r11*my + r12*mz;
    pz = r20*mx + r21*my + r22*mz;
    a2 = px*px + py*py + pz*pz;
}

__global__ __launch_bounds__(TPB, 1) void fused_kernel(
    const float* __restrict__ pred_t,        // (8,500,3)
    const float* __restrict__ pred_r,        // (8,60,4)
    const float* __restrict__ pred_c,        // (8,60)
    const float* __restrict__ target_r,      // (8,1,500,3)
    const float* __restrict__ target_t,      // (8,3,80,80)
    const float* __restrict__ model_points,  // (8,1,500,3)
    const int*   __restrict__ choose,        // (8,500)
    const int*   __restrict__ symmetric,     // (8,) bool->int32
    const float* __restrict__ diameters,     // (8,)
    const float* __restrict__ rot_anchors,   // (60,4)
    float*       __restrict__ out)           // 4 floats
{
    __shared__ float4 tg[2][NPTS];   // up to two batch tiles: (-2t, |t|^2)
    __shared__ float  red[32];
    __shared__ int    s_last;

    const int tid  = threadIdx.x;
    const int lane = tid & 31;
    const int wid  = tid >> 5;
    const int blk  = blockIdx.x;

    // ---- balanced du assignment: 3750 = 148*25 + 50 ----
    const int cnt = 25 + (blk < 50 ? 1 : 0);
    const int duS = 25 * blk + (blk < 50 ? blk : 50);
    const int gS  = duS * 64;
    const int gE  = (duS + cnt) * 64;
    const int b0  = gS / (NROT * NPTS);            // first batch in range
    const int bL  = (gE - 1) / (NROT * NPTS);      // last batch (<= b0+1)

    // ---- tile prologue: coalesced float4 preprocessing; both tiles in parallel
    if (tid < 125) {
        const float4* tp4 = reinterpret_cast<const float4*>(target_r + (size_t)b0 * NPTS * 3);
        float4 f0 = tp4[3*tid], f1 = tp4[3*tid+1], f2 = tp4[3*tid+2];
        tg[0][4*tid+0] = make_float4(-2.f*f0.x, -2.f*f0.y, -2.f*f0.z, f0.x*f0.x+f0.y*f0.y+f0.z*f0.z);
        tg[0][4*tid+1] = make_float4(-2.f*f0.w, -2.f*f1.x, -2.f*f1.y, f0.w*f0.w+f1.x*f1.x+f1.y*f1.y);
        tg[0][4*tid+2] = make_float4(-2.f*f1.z, -2.f*f1.w, -2.f*f2.x, f1.z*f1.z+f1.w*f1.w+f2.x*f2.x);
        tg[0][4*tid+3] = make_float4(-2.f*f2.y, -2.f*f2.z, -2.f*f2.w, f2.y*f2.y+f2.z*f2.z+f2.w*f2.w);
    } else if (bL != b0 && tid >= 128 && tid < 253) {
        int t = tid - 128;
        const float4* tp4 = reinterpret_cast<const float4*>(target_r + (size_t)bL * NPTS * 3);
        float4 f0 = tp4[3*t], f1 = tp4[3*t+1], f2 = tp4[3*t+2];
        tg[1][4*t+0] = make_float4(-2.f*f0.x, -2.f*f0.y, -2.f*f0.z, f0.x*f0.x+f0.y*f0.y+f0.z*f0.z);
        tg[1][4*t+1] = make_float4(-2.f*f0.w, -2.f*f1.x, -2.f*f1.y, f0.w*f0.w+f1.x*f1.x+f1.y*f1.y);
        tg[1][4*t+2] = make_float4(-2.f*f1.z, -2.f*f1.w, -2.f*f2.x, f1.z*f1.z+f1.w*f1.w+f2.x*f2.x);
        tg[1][4*t+3] = make_float4(-2.f*f2.y, -2.f*f2.z, -2.f*f2.w, f2.y*f2.y+f2.z*f2.z+f2.w*f2.w);
    }
    __syncthreads();

    // ---- chamfer: warp w handles double-unit duS + w ----
    if (wid < cnt) {
        const int du = duS + wid;
        const int g1 = du * 64 + lane;
        const int g2 = g1 + 32;
        const int br1 = g1 / NPTS, n1 = g1 - br1 * NPTS, b1 = g1 / (NROT*NPTS);
        const int br2 = g2 / NPTS, n2 = g2 - br2 * NPTS, b2 = g2 / (NROT*NPTS);

        float p1x, p1y, p1z, a21, p2x, p2y, p2z, a22;
        rot_point(pred_r, model_points, br1, b1, n1, p1x, p1y, p1z, a21);
        rot_point(pred_r, model_points, br2, b2, n2, p2x, p2y, p2z, a22);

        const float INF = 3.4e38f;
        float mnA1 = INF, mnB1 = INF, mnA2 = INF, mnB2 = INF;

        // warp-uniform: does this du's 64-range stay within one batch?
        const bool same = ((du*64) / (NROT*NPTS)) == ((du*64 + 63) / (NROT*NPTS));
        if (same) {
            const float4* T0 = tg[b1 - b0];
            for (int j0 = 0; j0 < NPTS; j0 += CHUNK) {
                float4 T[CHUNK];
                #pragma unroll
                for (int k = 0; k < CHUNK; k++) T[k] = T0[j0 + k];
                #pragma unroll
                for (int k = 0; k < CHUNK; k++) {
                    float s1 = fmaf(p1x, T[k].x, fmaf(p1y, T[k].y, fmaf(p1z, T[k].z, T[k].w)));
                    float s2 = fmaf(p2x, T[k].x, fmaf(p2y, T[k].y, fmaf(p2z, T[k].z, T[k].w)));
                    if (k & 1) { mnB1 = fminf(mnB1, s1); mnB2 = fminf(mnB2, s2); }
                    else       { mnA1 = fminf(mnA1, s1); mnA2 = fminf(mnA2, s2); }
                }
            }
        } else {
            // rare straddle (<= 7 warps grid-wide): per-thread tile pointers
            const float4* Tp1 = tg[b1 - b0];
            const float4* Tp2 = tg[b2 - b0];
            for (int j = 0; j < NPTS; j++) {
                float4 Ta = Tp1[j], Tb = Tp2[j];
                float s1 = fmaf(p1x, Ta.x, fmaf(p1y, Ta.y, fmaf(p1z, Ta.z, Ta.w)));
                float s2 = fmaf(p2x, Tb.x, fmaf(p2y, Tb.y, fmaf(p2z, Tb.z, Tb.w)));
                if (j & 1) { mnB1 = fminf(mnB1, s1); mnB2 = fminf(mnB2, s2); }
                else       { mnA1 = fminf(mnA1, s1); mnA2 = fminf(mnA2, s2); }
            }
        }

        float d1 = sqrtf(fmaxf(a21 + fminf(mnA1, mnB1), 1e-12f));
        float d2 = sqrtf(fmaxf(a22 + fminf(mnA2, mnB2), 1e-12f));

        float ns1 = 0.f, ns2 = 0.f;
        if (symmetric[b1] == 0) {
            float4 t = tg[b1 - b0][n1];       // t = -0.5 * tg.xyz
            float dx = fmaf(0.5f, t.x, p1x), dy = fmaf(0.5f, t.y, p1y), dz = fmaf(0.5f, t.z, p1z);
            ns1 = sqrtf(dx*dx + dy*dy + dz*dz);
        }
        if (symmetric[b2] == 0) {
            float4 t = tg[b2 - b0][n2];
            float dx = fmaf(0.5f, t.x, p2x), dy = fmaf(0.5f, t.y, p2y), dz = fmaf(0.5f, t.z, p2z);
            ns2 = sqrtf(dx*dx + dy*dy + dz*dz);
        }

        // segmented (by br) warp reduction: du spans at most {br_lo, br_lo+1}
        const int br_lo = (du * 64) / NPTS;
        float sA = (br1 == br_lo ? d1 : 0.f) + (br2 == br_lo ? d2 : 0.f);
        float sB = (br1 == br_lo ? 0.f : d1) + (br2 == br_lo ? 0.f : d2);
        float nA = (br1 == br_lo ? ns1 : 0.f) + (br2 == br_lo ? ns2 : 0.f);
        float nB = (br1 == br_lo ? 0.f : ns1) + (br2 == br_lo ? 0.f : ns2);
        #pragma unroll
        for (int off = 16; off; off >>= 1) {
            sA += __shfl_down_sync(0xffffffffu, sA, off);
            sB += __shfl_down_sync(0xffffffffu, sB, off);
            nA += __shfl_down_sync(0xffffffffu, nA, off);
            nB += __shfl_down_sync(0xffffffffu, nB, off);
        }
        if (lane == 0) {
            g_symA[du] = sA;  g_symB[du] = sB;
            g_nsA[du]  = nA;  g_nsB[du]  = nB;
        }
    }

    // ---- extras (reg + huber) folded into block 147 ----
    if (blk == GRID - 1) {
        __syncthreads();                       // du work done; reuse tg smem
        float* anc = reinterpret_cast<float*>(tg);
        if (tid < NROT * 4) anc[tid] = rot_anchors[tid];
        __syncthreads();

        float regsum = 0.f;
        if (tid < NBR) {
            int r = tid % NROT;
            float q0 = pred_r[4*tid], q1 = pred_r[4*tid+1];
            float q2 = pred_r[4*tid+2], q3 = pred_r[4*tid+3];
            float mx = -3.4e38f, dg = 0.f;
            #pragma unroll 4
            for (int a = 0; a < NROT; a++) {
                float c = q0*anc[4*a] + q1*anc[4*a+1] + q2*anc[4*a+2] + q3*anc[4*a+3];
                mx = fmaxf(mx, c);
                if (a == r) dg = c;
            }
            float reg = mx - dg;
            regsum = (reg > 0.001f) ? reg : 0.f;
        }

        float tsum = 0.f;
        for (int i = tid; i < BS * NPTS; i += TPB) {
            int b  = i / NPTS;
            int ch = choose[i];
            const float* tb = target_t + (size_t)b * 3 * HW;
            float tv0 = tb[ch], tv1 = tb[HW + ch], tv2 = tb[2*HW + ch];
            float d0 = pred_t[3*i]   - tv0;
            float d1 = pred_t[3*i+1] - tv1;
            float d2 = pred_t[3*i+2] - tv2;
            float a0 = fabsf(d0), a1 = fabsf(d1), a2v = fabsf(d2);
            tsum += (a0 < 1.f) ? 0.5f*d0*d0 : (a0 - 0.5f);
            tsum += (a1 < 1.f) ? 0.5f*d1*d1 : (a1 - 0.5f);
            tsum += (a2v < 1.f) ? 0.5f*d2*d2 : (a2v - 0.5f);
        }

        #pragma unroll
        for (int off = 16; off; off >>= 1) {
            regsum += __shfl_down_sync(0xffffffffu, regsum, off);
            tsum   += __shfl_down_sync(0xffffffffu, tsum,   off);
        }
        __syncthreads();
        if (lane == 0) red[wid] = regsum;
        __syncthreads();
        if (tid == 0) {
            float s = 0.f;
            for (int k = 0; k < 32; k++) s += red[k];
            g_scal[0] = s * (1.0f / NBR);
        }
        __syncthreads();
        if (lane == 0) red[wid] = tsum;
        __syncthreads();
        if (tid == 0) {
            float s = 0.f;
            for (int k = 0; k < 32; k++) s += red[k];
            g_scal[1] = s * (1.0f / (BS*NPTS*3));
        }
    }

    // ---- grid completion: last block finalizes ----
    __threadfence();
    __syncthreads();
    if (tid == 0) {
        unsigned int ticket = atomicAdd(&g_cnt, 1u);
        s_last = (ticket == (unsigned)GRID - 1u) ? 1 : 0;
    }
    __syncthreads();

    if (s_last) {
        float lr = 0.f;
        if (tid < NBR) {
            const int i = tid;
            const int b = i / NROT;
            int duA = (i * NPTS) / 64;
            int duB = (i * NPTS + NPTS - 1) / 64;
            float ssum = 0.f, nsum = 0.f;
            for (int du = duA; du <= duB; du++) {
                int br_lo = (du * 64) / NPTS;
                if (br_lo == i) { ssum += g_symA[du]; nsum += g_nsA[du]; }
                else            { ssum += g_symB[du]; nsum += g_nsB[du]; }
            }
            float d = (symmetric[b] != 0) ? ssum * (1.0f/NPTS) : nsum * (1.0f/NPTS);
            float c = pred_c[i];
            lr = (d / (diameters[b] * c) + logf(c)) * (1.0f / NROT);
        }
        #pragma unroll
        for (int off = 16; off; off >>= 1)
            lr += __shfl_down_sync(0xffffffffu, lr, off);
        __syncthreads();
        if (lane == 0) red[wid] = lr;
        __syncthreads();
        if (tid == 0) {
            float lrt = 0.f;
            for (int k = 0; k < 32; k++) lrt += red[k];
            float lreg = g_scal[0];
            float lt   = g_scal[1];
            out[0] = lrt + 2.f * lreg + 5.f * lt;
            out[1] = lrt;
            out[2] = lreg;
            out[3] = lt;
            g_cnt = 0;   // reset for next graph replay
        }
    }
}

// ---------------------------------------------------------------------------
// Launch. Input order: pred_t, pred_r, pred_c, target_r, target_t,
//                      model_points, choose, symmetric, diameters, rot_anchors
// ---------------------------------------------------------------------------
extern "C" void kernel_launch(void* const* d_in, const int* in_sizes, int n_in,
                              void* d_out, int out_size)
{
    fused_kernel<<<GRID, TPB>>>(
        (const float*)d_in[0], (const float*)d_in[1], (const float*)d_in[2],
        (const float*)d_in[3], (const float*)d_in[4], (const float*)d_in[5],
        (const int*)d_in[6],   (const int*)d_in[7],   (const float*)d_in[8],
        (const float*)d_in[9], (float*)d_out);
}